// round 1
// baseline (speedup 1.0000x reference)
#include <cuda_runtime.h>

// Problem constants
#define B_ 8
#define S_ 1024
#define D_ 256
#define NR (B_*S_)   // 8192 rows

// Scratch (static device allocations — allowed)
__device__ float g_xq[NR*D_];          // rope(q)  [b,s,d]   8 MB
__device__ float g_xv[NR*D_];          // rope(v)  [b,s,d]   8 MB
__device__ float g_M [B_*16*16*16];    // M[b,h][e][f] (scaled by 1/sqrt(hd))
__device__ float g_W2[B_*D_*D_];       // per-batch effective weight [k][n]

typedef unsigned long long u64;

__device__ __forceinline__ u64 pk2(float lo, float hi){
    u64 r; asm("mov.b64 %0, {%1, %2};" : "=l"(r) : "f"(lo), "f"(hi)); return r;
}
__device__ __forceinline__ void fma2(u64& d, u64 a, u64 b){
    asm("fma.rn.f32x2 %0, %1, %2, %0;" : "+l"(d) : "l"(a), "l"(b));
}
__device__ __forceinline__ void upk2(u64 v, float& lo, float& hi){
    asm("mov.b64 {%0, %1}, %2;" : "=f"(lo), "=f"(hi) : "l"(v));
}

// ---------------------------------------------------------------------------
// K1: fused Q/V projection (NT GEMM) + bias + RoPE -> g_xq, g_xv
// grid (128, 8): y<4 -> q cols [y*64,..), y>=4 -> v. BM=64 BN=64 BK=32.
// ---------------------------------------------------------------------------
__global__ __launch_bounds__(256) void qv_rope_kernel(
    const float* __restrict__ X,
    const float* __restrict__ Wq, const float* __restrict__ bq,
    const float* __restrict__ Wv, const float* __restrict__ bv)
{
    __shared__ __align__(16) float As[32][66];   // [k][m]
    __shared__ __align__(16) float Bs[32][66];   // [k][n]
    const int t = threadIdx.x, tx = t & 15, ty = t >> 4;
    const int m0 = blockIdx.x * 64;
    const bool isQ = blockIdx.y < 4;
    const int nb = (blockIdx.y & 3) * 64;
    const float* __restrict__ W    = isQ ? Wq : Wv;
    const float* __restrict__ bias = isQ ? bq : bv;
    float* __restrict__ dst        = isQ ? g_xq : g_xv;

    u64 acc[4][2] = {};

    for (int kt = 0; kt < D_; kt += 32) {
        #pragma unroll
        for (int i = 0; i < 2; i++) {
            int idx = t + i*256;               // 0..511 float4 slots
            int row = idx >> 3;                // 0..63
            int c4  = (idx & 7) * 4;           // 0..28
            float4 a = *(const float4*)(X + (m0+row)*D_ + kt + c4);
            As[c4+0][row] = a.x; As[c4+1][row] = a.y;
            As[c4+2][row] = a.z; As[c4+3][row] = a.w;
            float4 w = *(const float4*)(W + (nb+row)*D_ + kt + c4);
            Bs[c4+0][row] = w.x; Bs[c4+1][row] = w.y;
            Bs[c4+2][row] = w.z; Bs[c4+3][row] = w.w;
        }
        __syncthreads();
        #pragma unroll
        for (int kk = 0; kk < 32; kk++) {
            float2 a01 = *(const float2*)&As[kk][ty*4];
            float2 a23 = *(const float2*)&As[kk][ty*4+2];
            u64 b0 = *(const u64*)&Bs[kk][tx*4];
            u64 b1 = *(const u64*)&Bs[kk][tx*4+2];
            u64 ad;
            ad = pk2(a01.x, a01.x); fma2(acc[0][0], ad, b0); fma2(acc[0][1], ad, b1);
            ad = pk2(a01.y, a01.y); fma2(acc[1][0], ad, b0); fma2(acc[1][1], ad, b1);
            ad = pk2(a23.x, a23.x); fma2(acc[2][0], ad, b0); fma2(acc[2][1], ad, b1);
            ad = pk2(a23.y, a23.y); fma2(acc[3][0], ad, b0); fma2(acc[3][1], ad, b1);
        }
        __syncthreads();
    }

    // Epilogue: bias + RoPE (pairs (d, d+1); theta = 1 for d<128 else 1e-4)
    #pragma unroll
    for (int mi = 0; mi < 4; mi++) {
        int r = m0 + ty*4 + mi;
        float pos = (float)((r & (S_-1)) + 1);   // 1-indexed position
        int rbase = r * D_;
        #pragma unroll
        for (int np = 0; np < 2; np++) {
            int d = nb + tx*4 + np*2;
            float lo, hi; upk2(acc[mi][np], lo, hi);
            float xe = lo + bias[d];
            float xo = hi + bias[d+1];
            int jp = d >> 1;
            float th = (jp < 64) ? 1.0f : 1e-4f;
            float sv, cv; sincosf(pos * th, &sv, &cv);
            dst[rbase + d]     = xe*sv - xo*cv;   // real
            dst[rbase + d + 1] = xe*cv + xo*sv;   // imag
        }
    }
}

// ---------------------------------------------------------------------------
// K2: M[b,h][e][f] = (1/sqrt(16)) * sum_s xq[b,s,16h+e]*xv[b,s,16h+f]
// 128 blocks, 256 threads = 16 groups x 16 threads; group g sums 8 rows of
// each 128-row chunk; per-thread 4x4 register tile; cross-group reduce in smem.
// ---------------------------------------------------------------------------
__global__ __launch_bounds__(256) void m_kernel()
{
    const int bh = blockIdx.x, b = bh >> 4, h = bh & 15;
    const float* __restrict__ q = g_xq + b*S_*D_ + h*16;
    const float* __restrict__ v = g_xv + b*S_*D_ + h*16;
    __shared__ __align__(16) float qs[128][20];
    __shared__ __align__(16) float vs[128][20];
    __shared__ float part[16][16][17];
    const int t = threadIdx.x;
    const int g = t >> 4, lt = t & 15;
    const int e4 = (lt >> 2) * 4, f4 = (lt & 3) * 4;
    float c[4][4] = {};

    for (int chunk = 0; chunk < 8; chunk++) {
        int sb = chunk * 128;
        #pragma unroll
        for (int i = 0; i < 2; i++) {
            int idx = t + i*256;          // 512 float4 per array
            int row = idx >> 2, c4 = (idx & 3) * 4;
            *(float4*)&qs[row][c4] = *(const float4*)(q + (sb+row)*D_ + c4);
            *(float4*)&vs[row][c4] = *(const float4*)(v + (sb+row)*D_ + c4);
        }
        __syncthreads();
        int r0 = g * 8;
        #pragma unroll
        for (int ss = 0; ss < 8; ss++) {
            float4 q4 = *(const float4*)&qs[r0+ss][e4];
            float4 v4 = *(const float4*)&vs[r0+ss][f4];
            c[0][0] += q4.x*v4.x; c[0][1] += q4.x*v4.y; c[0][2] += q4.x*v4.z; c[0][3] += q4.x*v4.w;
            c[1][0] += q4.y*v4.x; c[1][1] += q4.y*v4.y; c[1][2] += q4.y*v4.z; c[1][3] += q4.y*v4.w;
            c[2][0] += q4.z*v4.x; c[2][1] += q4.z*v4.y; c[2][2] += q4.z*v4.z; c[2][3] += q4.z*v4.w;
            c[3][0] += q4.w*v4.x; c[3][1] += q4.w*v4.y; c[3][2] += q4.w*v4.z; c[3][3] += q4.w*v4.w;
        }
        __syncthreads();
    }
    #pragma unroll
    for (int i = 0; i < 4; i++)
        #pragma unroll
        for (int j = 0; j < 4; j++)
            part[g][e4+i][f4+j] = c[i][j];
    __syncthreads();
    int e = t >> 4, f = t & 15;
    float s = 0.f;
    #pragma unroll
    for (int gg = 0; gg < 16; gg++) s += part[gg][e][f];
    g_M[bh*256 + t] = s * 0.25f;   // 1/sqrt(HD=16)
}

// ---------------------------------------------------------------------------
// K3: W2_b[16h+e][n] = sum_f M[b,h][e][f] * wo[n][16h+f]
// ---------------------------------------------------------------------------
__global__ __launch_bounds__(256) void w2_kernel(const float* __restrict__ Wo)
{
    const int bh = blockIdx.x, b = bh >> 4, h = bh & 15;
    __shared__ __align__(16) float wos[256][20];
    __shared__ float Ms[16][16];
    const int t = threadIdx.x;
    Ms[t >> 4][t & 15] = g_M[bh*256 + t];
    #pragma unroll
    for (int i = 0; i < 4; i++) {
        int idx = t + i*256;              // 1024 float4
        int row = idx >> 2, c4 = (idx & 3) * 4;
        *(float4*)&wos[row][c4] = *(const float4*)(Wo + row*D_ + h*16 + c4);
    }
    __syncthreads();
    const int n = t;
    float* outp = g_W2 + b*D_*D_ + (h*16)*D_ + n;
    #pragma unroll
    for (int e = 0; e < 16; e++) {
        float a = 0.f;
        #pragma unroll
        for (int f = 0; f < 16; f++) a += Ms[e][f] * wos[n][f];
        outp[e*D_] = a;
    }
}

// ---------------------------------------------------------------------------
// K4: out_b = xq_b @ W2_b + bo   (NN GEMM, per batch via grid.z)
// ---------------------------------------------------------------------------
__global__ __launch_bounds__(256) void out_kernel(
    const float* __restrict__ bo, float* __restrict__ out)
{
    __shared__ __align__(16) float As[32][66];   // [k][m]
    __shared__ __align__(16) float Bs[32][66];   // [k][n]
    const int t = threadIdx.x, tx = t & 15, ty = t >> 4;
    const int bz = blockIdx.z;
    const int m0 = blockIdx.y * 64, n0 = blockIdx.x * 64;
    const float* __restrict__ A  = g_xq + bz*S_*D_;
    const float* __restrict__ Bw = g_W2 + bz*D_*D_;

    u64 acc[4][2] = {};

    for (int kt = 0; kt < D_; kt += 32) {
        #pragma unroll
        for (int i = 0; i < 2; i++) {
            int idx = t + i*256;
            int row = idx >> 3;
            int c4  = (idx & 7) * 4;
            float4 a = *(const float4*)(A + (m0+row)*D_ + kt + c4);
            As[c4+0][row] = a.x; As[c4+1][row] = a.y;
            As[c4+2][row] = a.z; As[c4+3][row] = a.w;
            int rowk = idx >> 4;              // 0..31
            int c    = (idx & 15) * 4;        // 0..60
            float4 w = *(const float4*)(Bw + (kt+rowk)*D_ + n0 + c);
            *(float2*)&Bs[rowk][c]   = make_float2(w.x, w.y);
            *(float2*)&Bs[rowk][c+2] = make_float2(w.z, w.w);
        }
        __syncthreads();
        #pragma unroll
        for (int kk = 0; kk < 32; kk++) {
            float2 a01 = *(const float2*)&As[kk][ty*4];
            float2 a23 = *(const float2*)&As[kk][ty*4+2];
            u64 b0 = *(const u64*)&Bs[kk][tx*4];
            u64 b1 = *(const u64*)&Bs[kk][tx*4+2];
            u64 ad;
            ad = pk2(a01.x, a01.x); fma2(acc[0][0], ad, b0); fma2(acc[0][1], ad, b1);
            ad = pk2(a01.y, a01.y); fma2(acc[1][0], ad, b0); fma2(acc[1][1], ad, b1);
            ad = pk2(a23.x, a23.x); fma2(acc[2][0], ad, b0); fma2(acc[2][1], ad, b1);
            ad = pk2(a23.y, a23.y); fma2(acc[3][0], ad, b0); fma2(acc[3][1], ad, b1);
        }
        __syncthreads();
    }

    #pragma unroll
    for (int mi = 0; mi < 4; mi++) {
        int row = bz*S_ + m0 + ty*4 + mi;
        #pragma unroll
        for (int np = 0; np < 2; np++) {
            int d = n0 + tx*4 + np*2;
            float lo, hi; upk2(acc[mi][np], lo, hi);
            out[row*D_ + d]     = lo + bo[d];
            out[row*D_ + d + 1] = hi + bo[d+1];
        }
    }
}

// ---------------------------------------------------------------------------
extern "C" void kernel_launch(void* const* d_in, const int* in_sizes, int n_in,
                              void* d_out, int out_size)
{
    (void)in_sizes; (void)n_in; (void)out_size;
    const float* x   = (const float*)d_in[0];
    const float* wqw = (const float*)d_in[1];
    const float* wqb = (const float*)d_in[2];
    // d_in[3], d_in[4] = wk_w, wk_b : dead in reference
    const float* wvw = (const float*)d_in[5];
    const float* wvb = (const float*)d_in[6];
    const float* wow = (const float*)d_in[7];
    const float* wob = (const float*)d_in[8];
    float* out = (float*)d_out;

    qv_rope_kernel<<<dim3(128, 8), 256>>>(x, wqw, wqb, wvw, wvb);
    m_kernel<<<128, 256>>>();
    w2_kernel<<<128, 256>>>(wow);
    out_kernel<<<dim3(4, 16, 8), 256>>>(wob, out);
}

// round 2
// speedup vs baseline: 1.0012x; 1.0012x over previous
#include <cuda_runtime.h>

// Problem constants
#define B_ 8
#define S_ 1024
#define D_ 256
#define NR (B_*S_)   // 8192 rows

// Scratch (static device allocations — allowed)
__device__ float g_xq[NR*D_];          // rope(q)  [b,s,d]   8 MB
__device__ float g_xv[NR*D_];          // rope(v)  [b,s,d]   8 MB
__device__ float g_M [B_*16*16*16];    // M[b,h][e][f] (scaled by 1/sqrt(hd))
__device__ float g_W2[B_*D_*D_];       // per-batch effective weight [k][n]

typedef unsigned long long u64;

__device__ __forceinline__ u64 pk2(float lo, float hi){
    u64 r; asm("mov.b64 %0, {%1, %2};" : "=l"(r) : "f"(lo), "f"(hi)); return r;
}
__device__ __forceinline__ void fma2(u64& d, u64 a, u64 b){
    asm("fma.rn.f32x2 %0, %1, %2, %0;" : "+l"(d) : "l"(a), "l"(b));
}
__device__ __forceinline__ void upk2(u64 v, float& lo, float& hi){
    asm("mov.b64 {%0, %1}, %2;" : "=f"(lo), "=f"(hi) : "l"(v));
}

// ---------------------------------------------------------------------------
// K1: fused Q/V projection (NT GEMM) + bias + RoPE -> g_xq, g_xv
// grid (128, 8): y<4 -> q cols [y*64,..), y>=4 -> v. BM=64 BN=64 BK=32.
// ---------------------------------------------------------------------------
__global__ __launch_bounds__(256) void qv_rope_kernel(
    const float* __restrict__ X,
    const float* __restrict__ Wq, const float* __restrict__ bq,
    const float* __restrict__ Wv, const float* __restrict__ bv)
{
    __shared__ __align__(16) float As[32][66];   // [k][m]
    __shared__ __align__(16) float Bs[32][66];   // [k][n]
    const int t = threadIdx.x, tx = t & 15, ty = t >> 4;
    const int m0 = blockIdx.x * 64;
    const bool isQ = blockIdx.y < 4;
    const int nb = (blockIdx.y & 3) * 64;
    const float* __restrict__ W    = isQ ? Wq : Wv;
    const float* __restrict__ bias = isQ ? bq : bv;
    float* __restrict__ dst        = isQ ? g_xq : g_xv;

    u64 acc[4][2] = {};

    for (int kt = 0; kt < D_; kt += 32) {
        #pragma unroll
        for (int i = 0; i < 2; i++) {
            int idx = t + i*256;               // 0..511 float4 slots
            int row = idx >> 3;                // 0..63
            int c4  = (idx & 7) * 4;           // 0..28
            float4 a = *(const float4*)(X + (m0+row)*D_ + kt + c4);
            As[c4+0][row] = a.x; As[c4+1][row] = a.y;
            As[c4+2][row] = a.z; As[c4+3][row] = a.w;
            float4 w = *(const float4*)(W + (nb+row)*D_ + kt + c4);
            Bs[c4+0][row] = w.x; Bs[c4+1][row] = w.y;
            Bs[c4+2][row] = w.z; Bs[c4+3][row] = w.w;
        }
        __syncthreads();
        #pragma unroll
        for (int kk = 0; kk < 32; kk++) {
            float2 a01 = *(const float2*)&As[kk][ty*4];
            float2 a23 = *(const float2*)&As[kk][ty*4+2];
            u64 b0 = *(const u64*)&Bs[kk][tx*4];
            u64 b1 = *(const u64*)&Bs[kk][tx*4+2];
            u64 ad;
            ad = pk2(a01.x, a01.x); fma2(acc[0][0], ad, b0); fma2(acc[0][1], ad, b1);
            ad = pk2(a01.y, a01.y); fma2(acc[1][0], ad, b0); fma2(acc[1][1], ad, b1);
            ad = pk2(a23.x, a23.x); fma2(acc[2][0], ad, b0); fma2(acc[2][1], ad, b1);
            ad = pk2(a23.y, a23.y); fma2(acc[3][0], ad, b0); fma2(acc[3][1], ad, b1);
        }
        __syncthreads();
    }

    // Epilogue: bias + RoPE (pairs (d, d+1); theta = 1 for d<128 else 1e-4)
    #pragma unroll
    for (int mi = 0; mi < 4; mi++) {
        int r = m0 + ty*4 + mi;
        float pos = (float)((r & (S_-1)) + 1);   // 1-indexed position
        int rbase = r * D_;
        #pragma unroll
        for (int np = 0; np < 2; np++) {
            int d = nb + tx*4 + np*2;
            float lo, hi; upk2(acc[mi][np], lo, hi);
            float xe = lo + bias[d];
            float xo = hi + bias[d+1];
            int jp = d >> 1;
            float th = (jp < 64) ? 1.0f : 1e-4f;
            float sv, cv; sincosf(pos * th, &sv, &cv);
            dst[rbase + d]     = xe*sv - xo*cv;   // real
            dst[rbase + d + 1] = xe*cv + xo*sv;   // imag
        }
    }
}

// ---------------------------------------------------------------------------
// K2: M[b,h][e][f] = (1/sqrt(16)) * sum_s xq[b,s,16h+e]*xv[b,s,16h+f]
// 128 blocks, 256 threads = 16 groups x 16 threads; group g sums 8 rows of
// each 128-row chunk; per-thread 4x4 register tile; cross-group reduce in smem.
// ---------------------------------------------------------------------------
__global__ __launch_bounds__(256) void m_kernel()
{
    const int bh = blockIdx.x, b = bh >> 4, h = bh & 15;
    const float* __restrict__ q = g_xq + b*S_*D_ + h*16;
    const float* __restrict__ v = g_xv + b*S_*D_ + h*16;
    __shared__ __align__(16) float qs[128][20];
    __shared__ __align__(16) float vs[128][20];
    __shared__ float part[16][16][17];
    const int t = threadIdx.x;
    const int g = t >> 4, lt = t & 15;
    const int e4 = (lt >> 2) * 4, f4 = (lt & 3) * 4;
    float c[4][4] = {};

    for (int chunk = 0; chunk < 8; chunk++) {
        int sb = chunk * 128;
        #pragma unroll
        for (int i = 0; i < 2; i++) {
            int idx = t + i*256;          // 512 float4 per array
            int row = idx >> 2, c4 = (idx & 3) * 4;
            *(float4*)&qs[row][c4] = *(const float4*)(q + (sb+row)*D_ + c4);
            *(float4*)&vs[row][c4] = *(const float4*)(v + (sb+row)*D_ + c4);
        }
        __syncthreads();
        int r0 = g * 8;
        #pragma unroll
        for (int ss = 0; ss < 8; ss++) {
            float4 q4 = *(const float4*)&qs[r0+ss][e4];
            float4 v4 = *(const float4*)&vs[r0+ss][f4];
            c[0][0] += q4.x*v4.x; c[0][1] += q4.x*v4.y; c[0][2] += q4.x*v4.z; c[0][3] += q4.x*v4.w;
            c[1][0] += q4.y*v4.x; c[1][1] += q4.y*v4.y; c[1][2] += q4.y*v4.z; c[1][3] += q4.y*v4.w;
            c[2][0] += q4.z*v4.x; c[2][1] += q4.z*v4.y; c[2][2] += q4.z*v4.z; c[2][3] += q4.z*v4.w;
            c[3][0] += q4.w*v4.x; c[3][1] += q4.w*v4.y; c[3][2] += q4.w*v4.z; c[3][3] += q4.w*v4.w;
        }
        __syncthreads();
    }
    #pragma unroll
    for (int i = 0; i < 4; i++)
        #pragma unroll
        for (int j = 0; j < 4; j++)
            part[g][e4+i][f4+j] = c[i][j];
    __syncthreads();
    int e = t >> 4, f = t & 15;
    float s = 0.f;
    #pragma unroll
    for (int gg = 0; gg < 16; gg++) s += part[gg][e][f];
    g_M[bh*256 + t] = s * 0.25f;   // 1/sqrt(HD=16)
}

// ---------------------------------------------------------------------------
// K3: W2_b[16h+e][n] = sum_f M[b,h][e][f] * wo[n][16h+f]
// ---------------------------------------------------------------------------
__global__ __launch_bounds__(256) void w2_kernel(const float* __restrict__ Wo)
{
    const int bh = blockIdx.x, b = bh >> 4, h = bh & 15;
    __shared__ __align__(16) float wos[256][20];
    __shared__ float Ms[16][16];
    const int t = threadIdx.x;
    Ms[t >> 4][t & 15] = g_M[bh*256 + t];
    #pragma unroll
    for (int i = 0; i < 4; i++) {
        int idx = t + i*256;              // 1024 float4
        int row = idx >> 2, c4 = (idx & 3) * 4;
        *(float4*)&wos[row][c4] = *(const float4*)(Wo + row*D_ + h*16 + c4);
    }
    __syncthreads();
    const int n = t;
    float* outp = g_W2 + b*D_*D_ + (h*16)*D_ + n;
    #pragma unroll
    for (int e = 0; e < 16; e++) {
        float a = 0.f;
        #pragma unroll
        for (int f = 0; f < 16; f++) a += Ms[e][f] * wos[n][f];
        outp[e*D_] = a;
    }
}

// ---------------------------------------------------------------------------
// K4: out_b = xq_b @ W2_b + bo   (NN GEMM, per batch via grid.z)
// ---------------------------------------------------------------------------
__global__ __launch_bounds__(256) void out_kernel(
    const float* __restrict__ bo, float* __restrict__ out)
{
    __shared__ __align__(16) float As[32][66];   // [k][m]
    __shared__ __align__(16) float Bs[32][66];   // [k][n]
    const int t = threadIdx.x, tx = t & 15, ty = t >> 4;
    const int bz = blockIdx.z;
    const int m0 = blockIdx.y * 64, n0 = blockIdx.x * 64;
    const float* __restrict__ A  = g_xq + bz*S_*D_;
    const float* __restrict__ Bw = g_W2 + bz*D_*D_;

    u64 acc[4][2] = {};

    for (int kt = 0; kt < D_; kt += 32) {
        #pragma unroll
        for (int i = 0; i < 2; i++) {
            int idx = t + i*256;
            int row = idx >> 3;
            int c4  = (idx & 7) * 4;
            float4 a = *(const float4*)(A + (m0+row)*D_ + kt + c4);
            As[c4+0][row] = a.x; As[c4+1][row] = a.y;
            As[c4+2][row] = a.z; As[c4+3][row] = a.w;
            int rowk = idx >> 4;              // 0..31
            int c    = (idx & 15) * 4;        // 0..60
            float4 w = *(const float4*)(Bw + (kt+rowk)*D_ + n0 + c);
            *(float2*)&Bs[rowk][c]   = make_float2(w.x, w.y);
            *(float2*)&Bs[rowk][c+2] = make_float2(w.z, w.w);
        }
        __syncthreads();
        #pragma unroll
        for (int kk = 0; kk < 32; kk++) {
            float2 a01 = *(const float2*)&As[kk][ty*4];
            float2 a23 = *(const float2*)&As[kk][ty*4+2];
            u64 b0 = *(const u64*)&Bs[kk][tx*4];
            u64 b1 = *(const u64*)&Bs[kk][tx*4+2];
            u64 ad;
            ad = pk2(a01.x, a01.x); fma2(acc[0][0], ad, b0); fma2(acc[0][1], ad, b1);
            ad = pk2(a01.y, a01.y); fma2(acc[1][0], ad, b0); fma2(acc[1][1], ad, b1);
            ad = pk2(a23.x, a23.x); fma2(acc[2][0], ad, b0); fma2(acc[2][1], ad, b1);
            ad = pk2(a23.y, a23.y); fma2(acc[3][0], ad, b0); fma2(acc[3][1], ad, b1);
        }
        __syncthreads();
    }

    #pragma unroll
    for (int mi = 0; mi < 4; mi++) {
        int row = bz*S_ + m0 + ty*4 + mi;
        #pragma unroll
        for (int np = 0; np < 2; np++) {
            int d = n0 + tx*4 + np*2;
            float lo, hi; upk2(acc[mi][np], lo, hi);
            out[row*D_ + d]     = lo + bo[d];
            out[row*D_ + d + 1] = hi + bo[d+1];
        }
    }
}

// ---------------------------------------------------------------------------
extern "C" void kernel_launch(void* const* d_in, const int* in_sizes, int n_in,
                              void* d_out, int out_size)
{
    (void)in_sizes; (void)n_in; (void)out_size;
    const float* x   = (const float*)d_in[0];
    const float* wqw = (const float*)d_in[1];
    const float* wqb = (const float*)d_in[2];
    // d_in[3], d_in[4] = wk_w, wk_b : dead in reference
    const float* wvw = (const float*)d_in[5];
    const float* wvb = (const float*)d_in[6];
    const float* wow = (const float*)d_in[7];
    const float* wob = (const float*)d_in[8];
    float* out = (float*)d_out;

    qv_rope_kernel<<<dim3(128, 8), 256>>>(x, wqw, wqb, wvw, wvb);
    m_kernel<<<128, 256>>>();
    w2_kernel<<<128, 256>>>(wow);
    out_kernel<<<dim3(4, 16, 8), 256>>>(wob, out);
}

// round 3
// speedup vs baseline: 1.0024x; 1.0012x over previous
#include <cuda_runtime.h>

// Problem constants
#define B_ 8
#define S_ 1024
#define D_ 256
#define NR (B_*S_)   // 8192 rows

// Scratch (static device allocations — allowed)
__device__ float g_xq[NR*D_];          // rope(q)  [b,s,d]   8 MB
__device__ float g_xv[NR*D_];          // rope(v)  [b,s,d]   8 MB
__device__ float g_M [B_*16*16*16];    // M[b,h][e][f] (scaled by 1/sqrt(hd))
__device__ float g_W2[B_*D_*D_];       // per-batch effective weight [k][n]

typedef unsigned long long u64;

__device__ __forceinline__ u64 pk2(float lo, float hi){
    u64 r; asm("mov.b64 %0, {%1, %2};" : "=l"(r) : "f"(lo), "f"(hi)); return r;
}
__device__ __forceinline__ void fma2(u64& d, u64 a, u64 b){
    asm("fma.rn.f32x2 %0, %1, %2, %0;" : "+l"(d) : "l"(a), "l"(b));
}
__device__ __forceinline__ void upk2(u64 v, float& lo, float& hi){
    asm("mov.b64 {%0, %1}, %2;" : "=f"(lo), "=f"(hi) : "l"(v));
}

// ---------------------------------------------------------------------------
// K1: fused Q/V projection (NT GEMM) + bias + RoPE -> g_xq, g_xv
// grid (128, 8): y<4 -> q cols [y*64,..), y>=4 -> v. BM=64 BN=64 BK=32.
// ---------------------------------------------------------------------------
__global__ __launch_bounds__(256) void qv_rope_kernel(
    const float* __restrict__ X,
    const float* __restrict__ Wq, const float* __restrict__ bq,
    const float* __restrict__ Wv, const float* __restrict__ bv)
{
    __shared__ __align__(16) float As[32][66];   // [k][m]
    __shared__ __align__(16) float Bs[32][66];   // [k][n]
    const int t = threadIdx.x, tx = t & 15, ty = t >> 4;
    const int m0 = blockIdx.x * 64;
    const bool isQ = blockIdx.y < 4;
    const int nb = (blockIdx.y & 3) * 64;
    const float* __restrict__ W    = isQ ? Wq : Wv;
    const float* __restrict__ bias = isQ ? bq : bv;
    float* __restrict__ dst        = isQ ? g_xq : g_xv;

    u64 acc[4][2] = {};

    for (int kt = 0; kt < D_; kt += 32) {
        #pragma unroll
        for (int i = 0; i < 2; i++) {
            int idx = t + i*256;               // 0..511 float4 slots
            int row = idx >> 3;                // 0..63
            int c4  = (idx & 7) * 4;           // 0..28
            float4 a = *(const float4*)(X + (m0+row)*D_ + kt + c4);
            As[c4+0][row] = a.x; As[c4+1][row] = a.y;
            As[c4+2][row] = a.z; As[c4+3][row] = a.w;
            float4 w = *(const float4*)(W + (nb+row)*D_ + kt + c4);
            Bs[c4+0][row] = w.x; Bs[c4+1][row] = w.y;
            Bs[c4+2][row] = w.z; Bs[c4+3][row] = w.w;
        }
        __syncthreads();
        #pragma unroll
        for (int kk = 0; kk < 32; kk++) {
            float2 a01 = *(const float2*)&As[kk][ty*4];
            float2 a23 = *(const float2*)&As[kk][ty*4+2];
            u64 b0 = *(const u64*)&Bs[kk][tx*4];
            u64 b1 = *(const u64*)&Bs[kk][tx*4+2];
            u64 ad;
            ad = pk2(a01.x, a01.x); fma2(acc[0][0], ad, b0); fma2(acc[0][1], ad, b1);
            ad = pk2(a01.y, a01.y); fma2(acc[1][0], ad, b0); fma2(acc[1][1], ad, b1);
            ad = pk2(a23.x, a23.x); fma2(acc[2][0], ad, b0); fma2(acc[2][1], ad, b1);
            ad = pk2(a23.y, a23.y); fma2(acc[3][0], ad, b0); fma2(acc[3][1], ad, b1);
        }
        __syncthreads();
    }

    // Epilogue: bias + RoPE (pairs (d, d+1); theta = 1 for d<128 else 1e-4)
    #pragma unroll
    for (int mi = 0; mi < 4; mi++) {
        int r = m0 + ty*4 + mi;
        float pos = (float)((r & (S_-1)) + 1);   // 1-indexed position
        int rbase = r * D_;
        #pragma unroll
        for (int np = 0; np < 2; np++) {
            int d = nb + tx*4 + np*2;
            float lo, hi; upk2(acc[mi][np], lo, hi);
            float xe = lo + bias[d];
            float xo = hi + bias[d+1];
            int jp = d >> 1;
            float th = (jp < 64) ? 1.0f : 1e-4f;
            float sv, cv; sincosf(pos * th, &sv, &cv);
            dst[rbase + d]     = xe*sv - xo*cv;   // real
            dst[rbase + d + 1] = xe*cv + xo*sv;   // imag
        }
    }
}

// ---------------------------------------------------------------------------
// K2: M[b,h][e][f] = (1/sqrt(16)) * sum_s xq[b,s,16h+e]*xv[b,s,16h+f]
// 128 blocks, 256 threads = 16 groups x 16 threads; group g sums 8 rows of
// each 128-row chunk; per-thread 4x4 register tile; cross-group reduce in smem.
// ---------------------------------------------------------------------------
__global__ __launch_bounds__(256) void m_kernel()
{
    const int bh = blockIdx.x, b = bh >> 4, h = bh & 15;
    const float* __restrict__ q = g_xq + b*S_*D_ + h*16;
    const float* __restrict__ v = g_xv + b*S_*D_ + h*16;
    __shared__ __align__(16) float qs[128][20];
    __shared__ __align__(16) float vs[128][20];
    __shared__ float part[16][16][17];
    const int t = threadIdx.x;
    const int g = t >> 4, lt = t & 15;
    const int e4 = (lt >> 2) * 4, f4 = (lt & 3) * 4;
    float c[4][4] = {};

    for (int chunk = 0; chunk < 8; chunk++) {
        int sb = chunk * 128;
        #pragma unroll
        for (int i = 0; i < 2; i++) {
            int idx = t + i*256;          // 512 float4 per array
            int row = idx >> 2, c4 = (idx & 3) * 4;
            *(float4*)&qs[row][c4] = *(const float4*)(q + (sb+row)*D_ + c4);
            *(float4*)&vs[row][c4] = *(const float4*)(v + (sb+row)*D_ + c4);
        }
        __syncthreads();
        int r0 = g * 8;
        #pragma unroll
        for (int ss = 0; ss < 8; ss++) {
            float4 q4 = *(const float4*)&qs[r0+ss][e4];
            float4 v4 = *(const float4*)&vs[r0+ss][f4];
            c[0][0] += q4.x*v4.x; c[0][1] += q4.x*v4.y; c[0][2] += q4.x*v4.z; c[0][3] += q4.x*v4.w;
            c[1][0] += q4.y*v4.x; c[1][1] += q4.y*v4.y; c[1][2] += q4.y*v4.z; c[1][3] += q4.y*v4.w;
            c[2][0] += q4.z*v4.x; c[2][1] += q4.z*v4.y; c[2][2] += q4.z*v4.z; c[2][3] += q4.z*v4.w;
            c[3][0] += q4.w*v4.x; c[3][1] += q4.w*v4.y; c[3][2] += q4.w*v4.z; c[3][3] += q4.w*v4.w;
        }
        __syncthreads();
    }
    #pragma unroll
    for (int i = 0; i < 4; i++)
        #pragma unroll
        for (int j = 0; j < 4; j++)
            part[g][e4+i][f4+j] = c[i][j];
    __syncthreads();
    int e = t >> 4, f = t & 15;
    float s = 0.f;
    #pragma unroll
    for (int gg = 0; gg < 16; gg++) s += part[gg][e][f];
    g_M[bh*256 + t] = s * 0.25f;   // 1/sqrt(HD=16)
}

// ---------------------------------------------------------------------------
// K3: W2_b[16h+e][n] = sum_f M[b,h][e][f] * wo[n][16h+f]
// ---------------------------------------------------------------------------
__global__ __launch_bounds__(256) void w2_kernel(const float* __restrict__ Wo)
{
    const int bh = blockIdx.x, b = bh >> 4, h = bh & 15;
    __shared__ __align__(16) float wos[256][20];
    __shared__ float Ms[16][16];
    const int t = threadIdx.x;
    Ms[t >> 4][t & 15] = g_M[bh*256 + t];
    #pragma unroll
    for (int i = 0; i < 4; i++) {
        int idx = t + i*256;              // 1024 float4
        int row = idx >> 2, c4 = (idx & 3) * 4;
        *(float4*)&wos[row][c4] = *(const float4*)(Wo + row*D_ + h*16 + c4);
    }
    __syncthreads();
    const int n = t;
    float* outp = g_W2 + b*D_*D_ + (h*16)*D_ + n;
    #pragma unroll
    for (int e = 0; e < 16; e++) {
        float a = 0.f;
        #pragma unroll
        for (int f = 0; f < 16; f++) a += Ms[e][f] * wos[n][f];
        outp[e*D_] = a;
    }
}

// ---------------------------------------------------------------------------
// K4: out_b = xq_b @ W2_b + bo   (NN GEMM, per batch via grid.z)
// ---------------------------------------------------------------------------
__global__ __launch_bounds__(256) void out_kernel(
    const float* __restrict__ bo, float* __restrict__ out)
{
    __shared__ __align__(16) float As[32][66];   // [k][m]
    __shared__ __align__(16) float Bs[32][66];   // [k][n]
    const int t = threadIdx.x, tx = t & 15, ty = t >> 4;
    const int bz = blockIdx.z;
    const int m0 = blockIdx.y * 64, n0 = blockIdx.x * 64;
    const float* __restrict__ A  = g_xq + bz*S_*D_;
    const float* __restrict__ Bw = g_W2 + bz*D_*D_;

    u64 acc[4][2] = {};

    for (int kt = 0; kt < D_; kt += 32) {
        #pragma unroll
        for (int i = 0; i < 2; i++) {
            int idx = t + i*256;
            int row = idx >> 3;
            int c4  = (idx & 7) * 4;
            float4 a = *(const float4*)(A + (m0+row)*D_ + kt + c4);
            As[c4+0][row] = a.x; As[c4+1][row] = a.y;
            As[c4+2][row] = a.z; As[c4+3][row] = a.w;
            int rowk = idx >> 4;              // 0..31
            int c    = (idx & 15) * 4;        // 0..60
            float4 w = *(const float4*)(Bw + (kt+rowk)*D_ + n0 + c);
            *(float2*)&Bs[rowk][c]   = make_float2(w.x, w.y);
            *(float2*)&Bs[rowk][c+2] = make_float2(w.z, w.w);
        }
        __syncthreads();
        #pragma unroll
        for (int kk = 0; kk < 32; kk++) {
            float2 a01 = *(const float2*)&As[kk][ty*4];
            float2 a23 = *(const float2*)&As[kk][ty*4+2];
            u64 b0 = *(const u64*)&Bs[kk][tx*4];
            u64 b1 = *(const u64*)&Bs[kk][tx*4+2];
            u64 ad;
            ad = pk2(a01.x, a01.x); fma2(acc[0][0], ad, b0); fma2(acc[0][1], ad, b1);
            ad = pk2(a01.y, a01.y); fma2(acc[1][0], ad, b0); fma2(acc[1][1], ad, b1);
            ad = pk2(a23.x, a23.x); fma2(acc[2][0], ad, b0); fma2(acc[2][1], ad, b1);
            ad = pk2(a23.y, a23.y); fma2(acc[3][0], ad, b0); fma2(acc[3][1], ad, b1);
        }
        __syncthreads();
    }

    #pragma unroll
    for (int mi = 0; mi < 4; mi++) {
        int row = bz*S_ + m0 + ty*4 + mi;
        #pragma unroll
        for (int np = 0; np < 2; np++) {
            int d = n0 + tx*4 + np*2;
            float lo, hi; upk2(acc[mi][np], lo, hi);
            out[row*D_ + d]     = lo + bo[d];
            out[row*D_ + d + 1] = hi + bo[d+1];
        }
    }
}

// ---------------------------------------------------------------------------
extern "C" void kernel_launch(void* const* d_in, const int* in_sizes, int n_in,
                              void* d_out, int out_size)
{
    (void)in_sizes; (void)n_in; (void)out_size;
    const float* x   = (const float*)d_in[0];
    const float* wqw = (const float*)d_in[1];
    const float* wqb = (const float*)d_in[2];
    // d_in[3], d_in[4] = wk_w, wk_b : dead in reference
    const float* wvw = (const float*)d_in[5];
    const float* wvb = (const float*)d_in[6];
    const float* wow = (const float*)d_in[7];
    const float* wob = (const float*)d_in[8];
    float* out = (float*)d_out;

    qv_rope_kernel<<<dim3(128, 8), 256>>>(x, wqw, wqb, wvw, wvb);
    m_kernel<<<128, 256>>>();
    w2_kernel<<<128, 256>>>(wow);
    out_kernel<<<dim3(4, 16, 8), 256>>>(wob, out);
}

// round 4
// speedup vs baseline: 1.4591x; 1.4556x over previous
#include <cuda_runtime.h>

// Problem constants
#define B_ 8
#define S_ 1024
#define D_ 256
#define NR (B_*S_)   // 8192 rows

// Scratch (static device allocations — allowed)
__device__ float g_xq[NR*D_];          // rope(q)  [b,s,d]   8 MB
__device__ float g_xv[NR*D_];          // rope(v)  [b,s,d]   8 MB
__device__ float g_M [B_*16*16*16];    // M[b,h][e][f] (scaled by 1/sqrt(hd))
__device__ float g_W2[B_*D_*D_];       // per-batch effective weight [k][n]

// ---------------------------------------------------------------------------
// tf32 MMA helpers (m16n8k8, row.col, f32 accum) + 3xTF32 split for accuracy
// ---------------------------------------------------------------------------
__device__ __forceinline__ unsigned f2tf(float x){
    unsigned r; asm("cvt.rna.tf32.f32 %0, %1;" : "=r"(r) : "f"(x)); return r;
}
__device__ __forceinline__ void split_tf32(float x, unsigned& h, unsigned& l){
    h = f2tf(x);
    l = f2tf(x - __uint_as_float(h));
}
__device__ __forceinline__ void mma_tf32(float* d, const unsigned* a, const unsigned* b){
    asm volatile(
        "mma.sync.aligned.m16n8k8.row.col.f32.tf32.tf32.f32 "
        "{%0,%1,%2,%3}, {%4,%5,%6,%7}, {%8,%9}, {%0,%1,%2,%3};"
        : "+f"(d[0]), "+f"(d[1]), "+f"(d[2]), "+f"(d[3])
        : "r"(a[0]), "r"(a[1]), "r"(a[2]), "r"(a[3]),
          "r"(b[0]), "r"(b[1]));
}

// ---------------------------------------------------------------------------
// K1: fused Q/V projection (C = X @ W^T) + bias + RoPE -> g_xq / g_xv
// BM=128 BN=64 BK=32, 8 warps (4m x 2n), warp tile 32x32, 3xTF32 MMA.
// grid (64, 8): y<4 -> Q cols [y*64..), y>=4 -> V.
// ---------------------------------------------------------------------------
__global__ __launch_bounds__(256) void qv_rope_tc(
    const float* __restrict__ X,
    const float* __restrict__ Wq, const float* __restrict__ bq,
    const float* __restrict__ Wv, const float* __restrict__ bv)
{
    __shared__ __align__(16) float As[128][36];   // [m][k] pitch 36 -> conflict-free frag reads
    __shared__ __align__(16) float Bs[64][36];    // [n][k] (W rows are k-contiguous)
    const int t = threadIdx.x;
    const int lane = t & 31, warp = t >> 5;
    const int g = lane >> 2, tg = lane & 3;       // groupID, threadInGroup
    const int wm = warp & 3, wn = warp >> 2;      // 4 x 2 warp grid
    const int m0 = blockIdx.x * 128;
    const bool isQ = blockIdx.y < 4;
    const int nb = (blockIdx.y & 3) * 64;
    const float* __restrict__ W    = isQ ? Wq : Wv;
    const float* __restrict__ bias = isQ ? bq : bv;
    float* __restrict__ dst        = isQ ? g_xq : g_xv;

    float acc[2][4][4] = {};

    for (int kt = 0; kt < D_; kt += 32) {
        #pragma unroll
        for (int i = 0; i < 4; i++) {
            int idx = t + i*256;                   // 1024 float4 (128 rows x 8)
            int row = idx >> 3, c4 = (idx & 7) * 4;
            *(float4*)&As[row][c4] = *(const float4*)(X + (m0+row)*D_ + kt + c4);
        }
        #pragma unroll
        for (int i = 0; i < 2; i++) {
            int idx = t + i*256;                   // 512 float4 (64 rows x 8)
            int row = idx >> 3, c4 = (idx & 7) * 4;
            *(float4*)&Bs[row][c4] = *(const float4*)(W + (nb+row)*D_ + kt + c4);
        }
        __syncthreads();

        #pragma unroll
        for (int ks = 0; ks < 4; ks++) {
            const int kb = ks * 8;
            unsigned aH[2][4], aL[2][4], bH[4][2], bL[4][2];
            #pragma unroll
            for (int mi = 0; mi < 2; mi++) {
                int rb = wm*32 + mi*16;
                split_tf32(As[rb+g  ][kb+tg  ], aH[mi][0], aL[mi][0]);
                split_tf32(As[rb+g+8][kb+tg  ], aH[mi][1], aL[mi][1]);
                split_tf32(As[rb+g  ][kb+tg+4], aH[mi][2], aL[mi][2]);
                split_tf32(As[rb+g+8][kb+tg+4], aH[mi][3], aL[mi][3]);
            }
            #pragma unroll
            for (int ni = 0; ni < 4; ni++) {
                int nbase = wn*32 + ni*8;
                split_tf32(Bs[nbase+g][kb+tg  ], bH[ni][0], bL[ni][0]);
                split_tf32(Bs[nbase+g][kb+tg+4], bH[ni][1], bL[ni][1]);
            }
            #pragma unroll
            for (int mi = 0; mi < 2; mi++)
                #pragma unroll
                for (int ni = 0; ni < 4; ni++) {
                    mma_tf32(acc[mi][ni], aH[mi], bH[ni]);
                    mma_tf32(acc[mi][ni], aH[mi], bL[ni]);
                    mma_tf32(acc[mi][ni], aL[mi], bH[ni]);
                }
        }
        __syncthreads();
    }

    // Epilogue: bias + RoPE. Accumulator cols (2tg, 2tg+1) are exactly RoPE pairs.
    #pragma unroll
    for (int mi = 0; mi < 2; mi++) {
        #pragma unroll
        for (int half = 0; half < 2; half++) {
            int r = m0 + wm*32 + mi*16 + g + half*8;
            float pos = (float)((r & (S_-1)) + 1);     // 1-indexed position
            #pragma unroll
            for (int ni = 0; ni < 4; ni++) {
                int d = nb + wn*32 + ni*8 + 2*tg;
                float xe = acc[mi][ni][half*2+0] + bias[d];
                float xo = acc[mi][ni][half*2+1] + bias[d+1];
                float th = (d < 128) ? 1.0f : 1e-4f;   // theta per pair index
                float sv, cv; sincosf(pos * th, &sv, &cv);
                float2 o = make_float2(xe*sv - xo*cv, xe*cv + xo*sv);
                *(float2*)(dst + r*D_ + d) = o;
            }
        }
    }
}

// ---------------------------------------------------------------------------
// K2: M[b,h][e][f] = (1/sqrt(16)) * sum_s xq[b,s,16h+e]*xv[b,s,16h+f]
// ---------------------------------------------------------------------------
__global__ __launch_bounds__(256) void m_kernel()
{
    const int bh = blockIdx.x, b = bh >> 4, h = bh & 15;
    const float* __restrict__ q = g_xq + b*S_*D_ + h*16;
    const float* __restrict__ v = g_xv + b*S_*D_ + h*16;
    __shared__ __align__(16) float qs[128][20];
    __shared__ __align__(16) float vs[128][20];
    __shared__ float part[16][16][17];
    const int t = threadIdx.x;
    const int g = t >> 4, lt = t & 15;
    const int e4 = (lt >> 2) * 4, f4 = (lt & 3) * 4;
    float c[4][4] = {};

    for (int chunk = 0; chunk < 8; chunk++) {
        int sb = chunk * 128;
        #pragma unroll
        for (int i = 0; i < 2; i++) {
            int idx = t + i*256;
            int row = idx >> 2, c4 = (idx & 3) * 4;
            *(float4*)&qs[row][c4] = *(const float4*)(q + (sb+row)*D_ + c4);
            *(float4*)&vs[row][c4] = *(const float4*)(v + (sb+row)*D_ + c4);
        }
        __syncthreads();
        int r0 = g * 8;
        #pragma unroll
        for (int ss = 0; ss < 8; ss++) {
            float4 q4 = *(const float4*)&qs[r0+ss][e4];
            float4 v4 = *(const float4*)&vs[r0+ss][f4];
            c[0][0] += q4.x*v4.x; c[0][1] += q4.x*v4.y; c[0][2] += q4.x*v4.z; c[0][3] += q4.x*v4.w;
            c[1][0] += q4.y*v4.x; c[1][1] += q4.y*v4.y; c[1][2] += q4.y*v4.z; c[1][3] += q4.y*v4.w;
            c[2][0] += q4.z*v4.x; c[2][1] += q4.z*v4.y; c[2][2] += q4.z*v4.z; c[2][3] += q4.z*v4.w;
            c[3][0] += q4.w*v4.x; c[3][1] += q4.w*v4.y; c[3][2] += q4.w*v4.z; c[3][3] += q4.w*v4.w;
        }
        __syncthreads();
    }
    #pragma unroll
    for (int i = 0; i < 4; i++)
        #pragma unroll
        for (int j = 0; j < 4; j++)
            part[g][e4+i][f4+j] = c[i][j];
    __syncthreads();
    int e = t >> 4, f = t & 15;
    float s = 0.f;
    #pragma unroll
    for (int gg = 0; gg < 16; gg++) s += part[gg][e][f];
    g_M[bh*256 + t] = s * 0.25f;   // 1/sqrt(HD=16)
}

// ---------------------------------------------------------------------------
// K3: W2_b[16h+e][n] = sum_f M[b,h][e][f] * wo[n][16h+f]
// ---------------------------------------------------------------------------
__global__ __launch_bounds__(256) void w2_kernel(const float* __restrict__ Wo)
{
    const int bh = blockIdx.x, b = bh >> 4, h = bh & 15;
    __shared__ __align__(16) float wos[256][20];
    __shared__ float Ms[16][16];
    const int t = threadIdx.x;
    Ms[t >> 4][t & 15] = g_M[bh*256 + t];
    #pragma unroll
    for (int i = 0; i < 4; i++) {
        int idx = t + i*256;
        int row = idx >> 2, c4 = (idx & 3) * 4;
        *(float4*)&wos[row][c4] = *(const float4*)(Wo + row*D_ + h*16 + c4);
    }
    __syncthreads();
    const int n = t;
    float* outp = g_W2 + b*D_*D_ + (h*16)*D_ + n;
    #pragma unroll
    for (int e = 0; e < 16; e++) {
        float a = 0.f;
        #pragma unroll
        for (int f = 0; f < 16; f++) a += Ms[e][f] * wos[n][f];
        outp[e*D_] = a;
    }
}

// ---------------------------------------------------------------------------
// K4: out_b = xq_b @ W2_b + bo  (NN GEMM per batch), 3xTF32 MMA.
// BM=128 BN=64 BK=32, grid (4, 8, 8).
// ---------------------------------------------------------------------------
__global__ __launch_bounds__(256) void out_tc(
    const float* __restrict__ bo, float* __restrict__ out)
{
    __shared__ __align__(16) float As[128][36];   // [m][k]
    __shared__ __align__(16) float Bs[32][72];    // [k][n] pitch 72 -> banks (8tg+g) distinct
    const int t = threadIdx.x;
    const int lane = t & 31, warp = t >> 5;
    const int g = lane >> 2, tg = lane & 3;
    const int wm = warp & 3, wn = warp >> 2;
    const int bz = blockIdx.z;
    const int m0 = blockIdx.y * 128, n0 = blockIdx.x * 64;
    const float* __restrict__ A  = g_xq + bz*S_*D_;
    const float* __restrict__ Bw = g_W2 + bz*D_*D_;

    float acc[2][4][4] = {};

    for (int kt = 0; kt < D_; kt += 32) {
        #pragma unroll
        for (int i = 0; i < 4; i++) {
            int idx = t + i*256;
            int row = idx >> 3, c4 = (idx & 7) * 4;
            *(float4*)&As[row][c4] = *(const float4*)(A + (m0+row)*D_ + kt + c4);
        }
        #pragma unroll
        for (int i = 0; i < 2; i++) {
            int idx = t + i*256;                   // 512 float4 (32 rows x 16)
            int row = idx >> 4, c = (idx & 15) * 4;
            *(float4*)&Bs[row][c] = *(const float4*)(Bw + (kt+row)*D_ + n0 + c);
        }
        __syncthreads();

        #pragma unroll
        for (int ks = 0; ks < 4; ks++) {
            const int kb = ks * 8;
            unsigned aH[2][4], aL[2][4], bH[4][2], bL[4][2];
            #pragma unroll
            for (int mi = 0; mi < 2; mi++) {
                int rb = wm*32 + mi*16;
                split_tf32(As[rb+g  ][kb+tg  ], aH[mi][0], aL[mi][0]);
                split_tf32(As[rb+g+8][kb+tg  ], aH[mi][1], aL[mi][1]);
                split_tf32(As[rb+g  ][kb+tg+4], aH[mi][2], aL[mi][2]);
                split_tf32(As[rb+g+8][kb+tg+4], aH[mi][3], aL[mi][3]);
            }
            #pragma unroll
            for (int ni = 0; ni < 4; ni++) {
                int nbase = wn*32 + ni*8;
                split_tf32(Bs[kb+tg  ][nbase+g], bH[ni][0], bL[ni][0]);
                split_tf32(Bs[kb+tg+4][nbase+g], bH[ni][1], bL[ni][1]);
            }
            #pragma unroll
            for (int mi = 0; mi < 2; mi++)
                #pragma unroll
                for (int ni = 0; ni < 4; ni++) {
                    mma_tf32(acc[mi][ni], aH[mi], bH[ni]);
                    mma_tf32(acc[mi][ni], aH[mi], bL[ni]);
                    mma_tf32(acc[mi][ni], aL[mi], bH[ni]);
                }
        }
        __syncthreads();
    }

    #pragma unroll
    for (int mi = 0; mi < 2; mi++) {
        #pragma unroll
        for (int half = 0; half < 2; half++) {
            int r = bz*S_ + m0 + wm*32 + mi*16 + g + half*8;
            #pragma unroll
            for (int ni = 0; ni < 4; ni++) {
                int d = n0 + wn*32 + ni*8 + 2*tg;
                float2 o = make_float2(acc[mi][ni][half*2+0] + bo[d],
                                       acc[mi][ni][half*2+1] + bo[d+1]);
                *(float2*)(out + r*D_ + d) = o;
            }
        }
    }
}

// ---------------------------------------------------------------------------
extern "C" void kernel_launch(void* const* d_in, const int* in_sizes, int n_in,
                              void* d_out, int out_size)
{
    (void)in_sizes; (void)n_in; (void)out_size;
    const float* x   = (const float*)d_in[0];
    const float* wqw = (const float*)d_in[1];
    const float* wqb = (const float*)d_in[2];
    // d_in[3], d_in[4] = wk_w, wk_b : dead in reference
    const float* wvw = (const float*)d_in[5];
    const float* wvb = (const float*)d_in[6];
    const float* wow = (const float*)d_in[7];
    const float* wob = (const float*)d_in[8];
    float* out = (float*)d_out;

    qv_rope_tc<<<dim3(64, 8), 256>>>(x, wqw, wqb, wvw, wvb);
    m_kernel<<<128, 256>>>();
    w2_kernel<<<128, 256>>>(wow);
    out_tc<<<dim3(4, 8, 8), 256>>>(wob, out);
}